// round 1
// baseline (speedup 1.0000x reference)
#include <cuda_runtime.h>
#include <cstdint>

// TensorizedEmbedding: vocab=32000=(8,10,20,20), out=768=(4,4,6,8), ranks (1,16,16,16,1)
// Strategy: split TT-chain in the middle.
//   a = idx / 400  in [0,80)   -> T01[a] : [16 m01 x 16 r2]   (contract core0,core1 over r1)
//   b = idx % 400  in [0,400)  -> T23[b] : [16 r2 x 48 m23]   (contract core2,core3 over r3)
//   out[token][m01*48 + m23] = sum_r2 T01[a][m01][r2] * T23[b][r2][m23]
// Per-token cost drops 41K MACs -> 12288 MACs.

__device__ float g_T01[80 * 256];    // layout [a][r2][m01]  (transposed for float4 loads)
__device__ float g_T23[400 * 768];   // layout [b][r2][m23]

// ---------------------------------------------------------------------------
// T01[a][r2][m01] = sum_r1 core0[0][d0][m0][r1] * core1[r1][d1][m1][r2]
// a = d0*10 + d1, m01 = m0*4 + m1
__global__ void precompute_T01(const float* __restrict__ core0,
                               const float* __restrict__ core1) {
    int a  = blockIdx.x;          // 0..79
    int d0 = a / 10;
    int d1 = a - d0 * 10;
    int e  = threadIdx.x;         // 0..255
    int r2  = e & 15;
    int m01 = e >> 4;             // 0..15
    int m0 = m01 >> 2, m1 = m01 & 3;

    float s = 0.f;
#pragma unroll
    for (int r1 = 0; r1 < 16; ++r1) {
        float c0 = __ldg(core0 + ((d0 * 4 + m0) * 16 + r1));
        float c1 = __ldg(core1 + (((r1 * 10 + d1) * 4 + m1) * 16 + r2));
        s = fmaf(c0, c1, s);
    }
    g_T01[a * 256 + r2 * 16 + m01] = s;
}

// ---------------------------------------------------------------------------
// T23[b][r2][m23] = sum_r3 core2[r2][d2][m2][r3] * core3[r3][d3][m3][0]
// b = d2*20 + d3, m23 = m2*8 + m3
__global__ void precompute_T23(const float* __restrict__ core2,
                               const float* __restrict__ core3) {
    int i = blockIdx.x * blockDim.x + threadIdx.x;   // < 400*768
    if (i >= 400 * 768) return;
    int b = i / 768;
    int e = i - b * 768;
    int r2  = e / 48;
    int m23 = e - r2 * 48;
    int m2 = m23 >> 3, m3 = m23 & 7;
    int d2 = b / 20;
    int d3 = b - d2 * 20;

    float s = 0.f;
#pragma unroll
    for (int r3 = 0; r3 < 16; ++r3) {
        float c2 = __ldg(core2 + (((r2 * 20 + d2) * 6 + m2) * 16 + r3));
        float c3 = __ldg(core3 + ((r3 * 20 + d3) * 8 + m3));
        s = fmaf(c2, c3, s);
    }
    g_T23[i] = s;
}

// ---------------------------------------------------------------------------
// Main gather kernel: one warp per token. Lane tile = 4 (m01) x 6 (m23).
// lanes: g01 = lane>>3 (4 groups of 4 m01 rows), g23 = lane&7 (8 groups of 6 cols)
__global__ void __launch_bounds__(256)
tte_main(const int* __restrict__ x, float* __restrict__ out, int ntok) {
    int warp = blockIdx.x * (blockDim.x >> 5) + (threadIdx.x >> 5);
    if (warp >= ntok) return;
    int lane = threadIdx.x & 31;

    int idx = __ldg(x + warp);
    int a = idx / 400;
    int b = idx - a * 400;

    int g01 = lane >> 3;   // 0..3
    int g23 = lane & 7;    // 0..7

    const float* __restrict__ t01p = g_T01 + a * 256 + g01 * 4;   // [r2][16], take 4 m01
    const float* __restrict__ t23p = g_T23 + b * 768 + g23 * 6;   // [r2][48], take 6 cols

    float acc[4][6];
#pragma unroll
    for (int i = 0; i < 4; ++i)
#pragma unroll
        for (int j = 0; j < 6; ++j) acc[i][j] = 0.f;

#pragma unroll
    for (int r2 = 0; r2 < 16; ++r2) {
        float4 p  = __ldg((const float4*)(t01p + r2 * 16));
        float2 q0 = __ldg((const float2*)(t23p + r2 * 48));
        float2 q1 = __ldg((const float2*)(t23p + r2 * 48 + 2));
        float2 q2 = __ldg((const float2*)(t23p + r2 * 48 + 4));
        float pp[4] = {p.x, p.y, p.z, p.w};
        float qq[6] = {q0.x, q0.y, q1.x, q1.y, q2.x, q2.y};
#pragma unroll
        for (int i = 0; i < 4; ++i)
#pragma unroll
            for (int j = 0; j < 6; ++j)
                acc[i][j] = fmaf(pp[i], qq[j], acc[i][j]);
    }

    float* o = out + (size_t)warp * 768 + g23 * 6;
#pragma unroll
    for (int i = 0; i < 4; ++i) {
        float* orow = o + (g01 * 4 + i) * 48;
        *(float2*)(orow)     = make_float2(acc[i][0], acc[i][1]);
        *(float2*)(orow + 2) = make_float2(acc[i][2], acc[i][3]);
        *(float2*)(orow + 4) = make_float2(acc[i][4], acc[i][5]);
    }
}

// ---------------------------------------------------------------------------
extern "C" void kernel_launch(void* const* d_in, const int* in_sizes, int n_in,
                              void* d_out, int out_size) {
    const int*   x     = (const int*)d_in[0];
    const float* core0 = (const float*)d_in[1];
    const float* core1 = (const float*)d_in[2];
    const float* core2 = (const float*)d_in[3];
    const float* core3 = (const float*)d_in[4];
    float* out = (float*)d_out;

    int ntok = in_sizes[0];   // 32768

    precompute_T01<<<80, 256>>>(core0, core1);
    precompute_T23<<<(400 * 768 + 255) / 256, 256>>>(core2, core3);

    int warps_per_block = 256 / 32;
    int grid = (ntok + warps_per_block - 1) / warps_per_block;
    tte_main<<<grid, 256>>>(x, out, ntok);
}